// round 4
// baseline (speedup 1.0000x reference)
#include <cuda_runtime.h>
#include <math.h>

#define BB 64
#define SS 512
#define HH 768
#define NT 36
#define TSTART 34
#define TSTOP 35

// Scratch (device globals — no allocation allowed)
__device__ float g_emit [BB * SS * NT];   // leaky_relu(x@W+b)
__device__ float g_eemit[BB * SS * NT];   // exp(emit)
__device__ float g_lossb[BB];

// ---------------- f32x2 helpers (Blackwell packed fp32) ----------------
__device__ __forceinline__ unsigned long long pack2(float a, float b) {
    unsigned long long r;
    asm("mov.b64 %0, {%1, %2};" : "=l"(r) : "f"(a), "f"(b));
    return r;
}
__device__ __forceinline__ void unpack2(unsigned long long v, float& a, float& b) {
    asm("mov.b64 {%0, %1}, %2;" : "=f"(a), "=f"(b) : "l"(v));
}
__device__ __forceinline__ unsigned long long fma2(unsigned long long a,
                                                   unsigned long long b,
                                                   unsigned long long c) {
    unsigned long long d;
    asm("fma.rn.f32x2 %0, %1, %2, %3;" : "=l"(d) : "l"(a), "l"(b), "l"(c));
    return d;
}

// ---------------- Kernel 1: gather + skinny GEMM + leaky_relu + exp ----------------
// C[32768,36] = gathered_X[32768,768] @ W[768,36]; 256 rows/block, 2 rows/thread,
// accumulators packed over adjacent tag pairs (f32x2), W tile read via LDS.64.
__global__ __launch_bounds__(128) void gemm_kernel(
    const float* __restrict__ x1, const int* __restrict__ hidx,
    const float* __restrict__ W, const float* __restrict__ bias)
{
    __shared__ __align__(16) float Xs[256][33];
    __shared__ __align__(16) float Ws[32][36];
    __shared__ int src[256];

    const int tid  = threadIdx.x;
    const int lane = tid & 31;
    const int warp = tid >> 5;
    const int rowbase = blockIdx.x * 256;

    for (int r = tid; r < 256; r += 128) {
        int g = rowbase + r;
        int b = g >> 9;                     // g / 512
        src[r] = (b << 9) * HH + hidx[g] * HH;   // (b*512 + head)*768
    }

    unsigned long long accA[18], accB[18];
#pragma unroll
    for (int p = 0; p < 18; p++) { accA[p] = 0ull; accB[p] = 0ull; }

    __syncthreads();

    for (int kt = 0; kt < 24; kt++) {
        const int k0 = kt * 32;
        // W tile: 32 rows x 36 cols = 1152 contiguous floats
        float* wflat = &Ws[0][0];
#pragma unroll
        for (int it = 0; it < 9; it++) {
            int idx = tid + it * 128;
            wflat[idx] = W[k0 * 36 + idx];
        }
        // X tile: each warp stages 64 rows, coalesced 128B per row
        for (int r = warp; r < 256; r += 4) {
            Xs[r][lane] = x1[src[r] + k0 + lane];
        }
        __syncthreads();

#pragma unroll 4
        for (int kk = 0; kk < 32; kk++) {
            float xa0 = Xs[tid][kk];
            float xb0 = Xs[tid + 128][kk];
            unsigned long long xa = pack2(xa0, xa0);
            unsigned long long xb = pack2(xb0, xb0);
            const unsigned long long* wrow =
                reinterpret_cast<const unsigned long long*>(&Ws[kk][0]);
#pragma unroll
            for (int p = 0; p < 18; p++) {
                unsigned long long w2 = wrow[p];
                accA[p] = fma2(xa, w2, accA[p]);
                accB[p] = fma2(xb, w2, accB[p]);
            }
        }
        __syncthreads();
    }

    // Epilogue: bias + leaky_relu(0.01) + exp, two rows per thread
    const int r0 = rowbase + tid;
    const int r1 = rowbase + tid + 128;
    float* e0  = g_emit  + (long long)r0 * NT;
    float* ee0 = g_eemit + (long long)r0 * NT;
    float* e1  = g_emit  + (long long)r1 * NT;
    float* ee1 = g_eemit + (long long)r1 * NT;
#pragma unroll
    for (int p = 0; p < 18; p++) {
        float b0 = bias[2 * p], b1 = bias[2 * p + 1];
        float a, c;
        unpack2(accA[p], a, c);
        float v0 = a + b0; v0 = (v0 >= 0.f) ? v0 : 0.01f * v0;
        float v1 = c + b1; v1 = (v1 >= 0.f) ? v1 : 0.01f * v1;
        e0[2 * p] = v0;  e0[2 * p + 1] = v1;
        ee0[2 * p] = __expf(v0); ee0[2 * p + 1] = __expf(v1);
        unpack2(accB[p], a, c);
        v0 = a + b0; v0 = (v0 >= 0.f) ? v0 : 0.01f * v0;
        v1 = c + b1; v1 = (v1 >= 0.f) ? v1 : 0.01f * v1;
        e1[2 * p] = v0;  e1[2 * p + 1] = v1;
        ee1[2 * p] = __expf(v0); ee1[2 * p + 1] = __expf(v1);
    }
}

// ---------------- Kernel 2: CRF scans ----------------
// blocks [0,64):   scaled-forward NLL (prob domain, no exp in inner loop)
// blocks [64,128): Viterbi + shared-mem backpointers + backtrace
__global__ __launch_bounds__(64) void scan_kernel(
    const int* __restrict__ hidx, const int* __restrict__ tags,
    const float* __restrict__ trans, float* __restrict__ out)
{
    __shared__ float buf[2][NT];
    __shared__ float red[64];
    __shared__ int   ired[64];
    __shared__ int   sh_xlen;
    __shared__ int   sh_last;
    __shared__ __align__(16) char uu[(SS - 1) * NT];  // 18396B: Tsh (NLL) / bp (Viterbi)

    const int tid = threadIdx.x;
    const int b   = blockIdx.x & 63;
    const bool viterbi = (blockIdx.x >= BB);

    // xlen = max(head_indexes[b, :])
    {
        int lm = 0;
        for (int s = tid; s < SS; s += 64) lm = max(lm, hidx[b * SS + s]);
        ired[tid] = lm;
        __syncthreads();
        if (tid == 0) {
            int m = 0;
            for (int i = 0; i < 64; i++) m = max(m, ired[i]);
            sh_xlen = m;
        }
        __syncthreads();
    }
    const int xlen = sh_xlen;
    const int j = tid;

    if (!viterbi) {
        // ---------------- NLL (scaled forward) ----------------
        float* Tsh = reinterpret_cast<float*>(uu);
        for (int i = tid; i < NT * NT; i += 64) Tsh[i] = trans[i];
        __syncthreads();

        float Ecol[NT];
        float Cl = 0.f;
        if (j < NT) {
#pragma unroll
            for (int i = 0; i < NT; i++) Ecol[i] = __expf(Tsh[i * NT + j]);
            buf[0][j] = __expf(g_emit[(b * SS) * NT + j] + Tsh[TSTART * NT + j]);
        }
        __syncthreads();

        const float* ee = g_eemit + (long long)b * SS * NT;
        float eenext = (xlen > 1 && j < NT) ? ee[NT + j] : 0.f;
        for (int t = 1; t < xlen; t++) {
            const int cur = t & 1, prev = cur ^ 1;
            float eecur = eenext;
            if (t + 1 < xlen && j < NT) eenext = ee[(t + 1) * NT + j];
            if (j < NT) {
                float acc = 0.f, m = 0.f;
#pragma unroll
                for (int i = 0; i < NT; i++) {
                    float v = buf[prev][i];
                    acc = fmaf(v, Ecol[i], acc);
                    m = fmaxf(m, v);
                }
                buf[cur][j] = acc * (1.0f / m) * eecur;
                Cl += __logf(m);
            }
            __syncthreads();
        }
        const int lastbuf = (xlen >= 2) ? ((xlen - 1) & 1) : 0;
        if (j < NT) red[j] = buf[lastbuf][j] * __expf(Tsh[j * NT + TSTOP]);
        __syncthreads();

        float logZ = 0.f;
        if (tid == 0) {
            float sZ = 0.f;
            for (int i = 0; i < NT; i++) sZ += red[i];
            logZ = Cl + __logf(sZ);
        }
        __syncthreads();

        // gold score
        const int* tg = tags + b * SS;
        float gp = 0.f;
        for (int s = tid; s < xlen; s += 64) {
            int cs = tg[s];
            gp += g_emit[((long long)b * SS + s) * NT + cs];
            if (s >= 1) gp += Tsh[tg[s - 1] * NT + cs];
        }
        red[tid] = gp;
        __syncthreads();
        if (tid == 0) {
            float g = 0.f;
            for (int i = 0; i < 64; i++) g += red[i];
            int li = (xlen > 0) ? (xlen - 1) : 0;
            g += Tsh[TSTART * NT + tg[0]] + Tsh[tg[li] * NT + TSTOP];
            g_lossb[b] = logZ - g;
        }
    } else {
        // ---------------- Viterbi ----------------
        unsigned char* bp = reinterpret_cast<unsigned char*>(uu);
        float Tcol[NT];
        float TjS = 0.f;
        if (j < NT) {
#pragma unroll
            for (int i = 0; i < NT; i++) Tcol[i] = trans[i * NT + j];
            TjS = trans[j * NT + TSTOP];
            buf[0][j] = g_emit[(b * SS) * NT + j] + trans[TSTART * NT + j];
        }
        __syncthreads();

        const float* em = g_emit + (long long)b * SS * NT;
        float emnext = (xlen > 1 && j < NT) ? em[NT + j] : 0.f;
        for (int t = 1; t < xlen; t++) {
            const int cur = t & 1, prev = cur ^ 1;
            float ec = emnext;
            if (t + 1 < xlen && j < NT) emnext = em[(t + 1) * NT + j];
            if (j < NT) {
                float best = -1e30f;
                int bi = 0;
#pragma unroll
                for (int i = 0; i < NT; i++) {
                    float v = buf[prev][i] + Tcol[i];
                    if (v > best) { best = v; bi = i; }   // first max wins (jnp.argmax)
                }
                buf[cur][j] = best + ec;
                bp[(t - 1) * NT + j] = (unsigned char)bi;
            }
            __syncthreads();
        }
        const int lastbuf = (xlen >= 2) ? ((xlen - 1) & 1) : 0;
        if (j < NT) red[j] = buf[lastbuf][j] + TjS;
        __syncthreads();
        if (tid == 0) {
            float bs = -1e30f; int lt = 0;
            for (int i = 0; i < NT; i++) {
                float v = red[i];
                if (v > bs) { bs = v; lt = i; }
            }
            out[1 + BB * SS + b] = bs;   // path_score
            sh_last = lt;
        }
        __syncthreads();

        float* op = out + 1 + b * SS;
        for (int s = xlen + tid; s < SS; s += 64) op[s] = 0.f;  // masked tail
        if (tid == 0 && xlen > 0) {
            int tag = sh_last;
            op[xlen - 1] = (float)tag;
            for (int t = xlen - 1; t >= 1; t--) {
                tag = bp[(t - 1) * NT + tag];
                op[t - 1] = (float)tag;
            }
        }
    }
}

// ---------------- Kernel 3: deterministic loss reduction ----------------
__global__ void finish_kernel(float* __restrict__ out) {
    if (threadIdx.x == 0 && blockIdx.x == 0) {
        float a = 0.f;
        for (int i = 0; i < BB; i++) a += g_lossb[i];
        out[0] = a;
    }
}

extern "C" void kernel_launch(void* const* d_in, const int* in_sizes, int n_in,
                              void* d_out, int out_size) {
    const float* x1    = (const float*)d_in[0];
    const int*   hidx  = (const int*)  d_in[1];
    const int*   tags  = (const int*)  d_in[2];
    const float* W     = (const float*)d_in[3];
    const float* bias  = (const float*)d_in[4];
    const float* trans = (const float*)d_in[5];
    float* out = (float*)d_out;

    gemm_kernel<<<128, 128>>>(x1, hidx, W, bias);   // 32768 rows / 256 per block
    scan_kernel<<<128, 64>>>(hidx, tags, trans, out);
    finish_kernel<<<1, 32>>>(out);
}

// round 5
// speedup vs baseline: 1.5316x; 1.5316x over previous
#include <cuda_runtime.h>
#include <math.h>

#define BB 64
#define SS 512
#define HH 768
#define NT 36
#define TSTART 34
#define TSTOP 35

// Scratch (device globals — no allocation allowed)
__device__ float g_emit [BB * SS * NT];   // leaky_relu(x@W+b)
__device__ float g_eemit[BB * SS * NT];   // exp(emit)
__device__ float g_lossb[BB];

// ---------------- f32x2 helpers (Blackwell packed fp32) ----------------
__device__ __forceinline__ unsigned long long pack2(float a, float b) {
    unsigned long long r;
    asm("mov.b64 %0, {%1, %2};" : "=l"(r) : "f"(a), "f"(b));
    return r;
}
__device__ __forceinline__ void unpack2(unsigned long long v, float& a, float& b) {
    asm("mov.b64 {%0, %1}, %2;" : "=f"(a), "=f"(b) : "l"(v));
}
__device__ __forceinline__ unsigned long long fma2(unsigned long long a,
                                                   unsigned long long b,
                                                   unsigned long long c) {
    unsigned long long d;
    asm("fma.rn.f32x2 %0, %1, %2, %3;" : "=l"(d) : "l"(a), "l"(b), "l"(c));
    return d;
}
__device__ __forceinline__ unsigned long long add2(unsigned long long a,
                                                   unsigned long long b) {
    unsigned long long d;
    asm("add.rn.f32x2 %0, %1, %2;" : "=l"(d) : "l"(a), "l"(b));
    return d;
}

// ---------------- Kernel 1: gather + skinny GEMM + leaky_relu + exp ----------------
// 128 rows/block, 256 blocks. 256 threads: half = tid>>7 owns K range [half*384,+384).
// Each thread: 1 row, 36 cols as 18 f32x2 accumulators. W tile read via LDS.128
// directly into ulonglong2 (no pack movs). Halves combined through shared memory.
__global__ __launch_bounds__(256) void gemm_kernel(
    const float* __restrict__ x1, const int* __restrict__ hidx,
    const float* __restrict__ W, const float* __restrict__ bias)
{
    __shared__ __align__(16) float Xs[2][128][33];
    __shared__ __align__(16) float Ws[2][32][36];
    __shared__ int src[128];

    const int tid  = threadIdx.x;
    const int half = tid >> 7;
    const int r    = tid & 127;
    const int lane = tid & 31;
    const int w4   = (tid >> 5) & 3;
    const int rowbase = blockIdx.x * 128;

    if (tid < 128) {
        int g = rowbase + tid;
        int b = g >> 9;                          // g / 512
        src[tid] = (b << 9) * HH + hidx[g] * HH; // (b*512 + head)*768
    }

    unsigned long long acc[18];
#pragma unroll
    for (int p = 0; p < 18; p++) acc[p] = 0ull;

    __syncthreads();

    const int kbase = half * 384;
    for (int kt = 0; kt < 12; kt++) {
        const int k0 = kbase + kt * 32;
        // W tile: 32 rows x 36 cols = 1152 floats, by 128 threads of this half
        float* wf = &Ws[half][0][0];
#pragma unroll
        for (int it = 0; it < 9; it++)
            wf[r + it * 128] = W[k0 * 36 + r + it * 128];
        // X tile: each of the half's 4 warps stages 32 rows, 128B coalesced
        for (int rr = w4; rr < 128; rr += 4)
            Xs[half][rr][lane] = x1[src[rr] + k0 + lane];
        __syncthreads();

#pragma unroll 8
        for (int kk = 0; kk < 32; kk++) {
            float x = Xs[half][r][kk];
            unsigned long long xx = pack2(x, x);
            const ulonglong2* wrow =
                reinterpret_cast<const ulonglong2*>(&Ws[half][kk][0]);
#pragma unroll
            for (int p = 0; p < 9; p++) {
                ulonglong2 w = wrow[p];                 // LDS.128 broadcast
                acc[2 * p]     = fma2(xx, w.x, acc[2 * p]);
                acc[2 * p + 1] = fma2(xx, w.y, acc[2 * p + 1]);
            }
        }
        __syncthreads();
    }

    // Combine halves: half1 dumps partials to shared (reuse Xs), half0 finishes.
    float* sp = &Xs[0][0][0];   // 128*36 floats needed, 8448 available
    if (half == 1) {
#pragma unroll
        for (int q = 0; q < 18; q++) {
            float a, b; unpack2(acc[q], a, b);
            sp[r * 36 + 2 * q]     = a;
            sp[r * 36 + 2 * q + 1] = b;
        }
    }
    __syncthreads();
    if (half == 0) {
        const long long row = rowbase + r;
        float ev[36], eev[36];
#pragma unroll
        for (int q = 0; q < 18; q++) {
            float a, b; unpack2(acc[q], a, b);
            float v0 = a + sp[r * 36 + 2 * q]     + bias[2 * q];
            float v1 = b + sp[r * 36 + 2 * q + 1] + bias[2 * q + 1];
            v0 = (v0 >= 0.f) ? v0 : 0.01f * v0;
            v1 = (v1 >= 0.f) ? v1 : 0.01f * v1;
            ev[2 * q] = v0;  ev[2 * q + 1] = v1;
            eev[2 * q] = __expf(v0);  eev[2 * q + 1] = __expf(v1);
        }
        float4* pe  = reinterpret_cast<float4*>(g_emit  + row * 36);
        float4* pee = reinterpret_cast<float4*>(g_eemit + row * 36);
#pragma unroll
        for (int q = 0; q < 9; q++) {
            pe[q]  = make_float4(ev[4*q], ev[4*q+1], ev[4*q+2], ev[4*q+3]);
            pee[q] = make_float4(eev[4*q], eev[4*q+1], eev[4*q+2], eev[4*q+3]);
        }
    }
}

// ---------------- Kernel 2: CRF scans ----------------
// blocks [0,64):   scaled-forward NLL (prob domain, packed f32x2, 4 ILP chains)
// blocks [64,128): Viterbi (chunk-4 argmax, first-max preserved) + backtrace
__global__ __launch_bounds__(64) void scan_kernel(
    const int* __restrict__ hidx, const int* __restrict__ tags,
    const float* __restrict__ trans, float* __restrict__ out)
{
    __shared__ __align__(16) float buf[2][NT];
    __shared__ float red[64];
    __shared__ int   ired[64];
    __shared__ int   sh_xlen;
    __shared__ int   sh_last;
    __shared__ __align__(16) char uu[(SS - 1) * NT];  // Tsh (NLL) / bp (Viterbi)

    const int tid = threadIdx.x;
    const int b   = blockIdx.x & 63;
    const bool viterbi = (blockIdx.x >= BB);

    // xlen = max(head_indexes[b, :])
    {
        int lm = 0;
        for (int s = tid; s < SS; s += 64) lm = max(lm, hidx[b * SS + s]);
        ired[tid] = lm;
        __syncthreads();
        if (tid == 0) {
            int m = 0;
            for (int i = 0; i < 64; i++) m = max(m, ired[i]);
            sh_xlen = m;
        }
        __syncthreads();
    }
    const int xlen = sh_xlen;
    const int j = tid;

    if (!viterbi) {
        // ---------------- NLL (scaled forward, packed) ----------------
        float* Tsh = reinterpret_cast<float*>(uu);
        for (int i = tid; i < NT * NT; i += 64) Tsh[i] = trans[i];
        __syncthreads();

        unsigned long long Ecol2[18];   // exp(T[2p][j]), exp(T[2p+1][j])
        float Cl = 0.f;
        if (j < NT) {
#pragma unroll
            for (int p = 0; p < 18; p++)
                Ecol2[p] = pack2(__expf(Tsh[(2 * p) * NT + j]),
                                 __expf(Tsh[(2 * p + 1) * NT + j]));
            buf[0][j] = __expf(g_emit[(b * SS) * NT + j] + Tsh[TSTART * NT + j]);
        }
        __syncthreads();

        const float* ee = g_eemit + (long long)b * SS * NT;
        float eenext = (xlen > 1 && j < NT) ? ee[NT + j] : 0.f;
        for (int t = 1; t < xlen; t++) {
            const int cur = t & 1, prev = cur ^ 1;
            float eecur = eenext;
            if (t + 1 < xlen && j < NT) eenext = ee[(t + 1) * NT + j];
            if (j < NT) {
                const unsigned long long* vp =
                    reinterpret_cast<const unsigned long long*>(&buf[prev][0]);
                unsigned long long c0 = 0, c1 = 0, c2 = 0, c3 = 0;
                float m0 = 0.f, m1 = 0.f, m2 = 0.f, m3 = 0.f;
#pragma unroll
                for (int p = 0; p < 16; p += 4) {
                    unsigned long long v0 = vp[p], v1 = vp[p+1], v2 = vp[p+2], v3 = vp[p+3];
                    c0 = fma2(v0, Ecol2[p],   c0);
                    c1 = fma2(v1, Ecol2[p+1], c1);
                    c2 = fma2(v2, Ecol2[p+2], c2);
                    c3 = fma2(v3, Ecol2[p+3], c3);
                    float a, bb2;
                    unpack2(v0, a, bb2); m0 = fmaxf(m0, fmaxf(a, bb2));
                    unpack2(v1, a, bb2); m1 = fmaxf(m1, fmaxf(a, bb2));
                    unpack2(v2, a, bb2); m2 = fmaxf(m2, fmaxf(a, bb2));
                    unpack2(v3, a, bb2); m3 = fmaxf(m3, fmaxf(a, bb2));
                }
                {   // p = 16, 17
                    unsigned long long v0 = vp[16], v1 = vp[17];
                    c0 = fma2(v0, Ecol2[16], c0);
                    c1 = fma2(v1, Ecol2[17], c1);
                    float a, bb2;
                    unpack2(v0, a, bb2); m0 = fmaxf(m0, fmaxf(a, bb2));
                    unpack2(v1, a, bb2); m1 = fmaxf(m1, fmaxf(a, bb2));
                }
                unsigned long long cs = add2(add2(c0, c1), add2(c2, c3));
                float sa, sb; unpack2(cs, sa, sb);
                float accv = sa + sb;
                float m = fmaxf(fmaxf(m0, m1), fmaxf(m2, m3));
                buf[cur][j] = accv * (1.0f / m) * eecur;
                Cl += __logf(m);
            }
            __syncthreads();
        }
        const int lastbuf = (xlen >= 2) ? ((xlen - 1) & 1) : 0;
        if (j < NT) red[j] = buf[lastbuf][j] * __expf(Tsh[j * NT + TSTOP]);
        __syncthreads();

        float logZ = 0.f;
        if (tid == 0) {
            float sZ = 0.f;
            for (int i = 0; i < NT; i++) sZ += red[i];
            logZ = Cl + __logf(sZ);
        }
        __syncthreads();

        // gold score
        const int* tg = tags + b * SS;
        float gp = 0.f;
        for (int s = tid; s < xlen; s += 64) {
            int cs = tg[s];
            gp += g_emit[((long long)b * SS + s) * NT + cs];
            if (s >= 1) gp += Tsh[tg[s - 1] * NT + cs];
        }
        red[tid] = gp;
        __syncthreads();
        if (tid == 0) {
            float g = 0.f;
            for (int i = 0; i < 64; i++) g += red[i];
            int li = (xlen > 0) ? (xlen - 1) : 0;
            g += Tsh[TSTART * NT + tg[0]] + Tsh[tg[li] * NT + TSTOP];
            g_lossb[b] = logZ - g;
        }
    } else {
        // ---------------- Viterbi (chunk-4, first-max preserved) ----------------
        unsigned char* bp = reinterpret_cast<unsigned char*>(uu);
        float Tcol[NT];
        float TjS = 0.f;
        if (j < NT) {
#pragma unroll
            for (int i = 0; i < NT; i++) Tcol[i] = trans[i * NT + j];
            TjS = trans[j * NT + TSTOP];
            buf[0][j] = g_emit[(b * SS) * NT + j] + trans[TSTART * NT + j];
        }
        __syncthreads();

        const float* em = g_emit + (long long)b * SS * NT;
        float emnext = (xlen > 1 && j < NT) ? em[NT + j] : 0.f;
        for (int t = 1; t < xlen; t++) {
            const int cur = t & 1, prev = cur ^ 1;
            float ec = emnext;
            if (t + 1 < xlen && j < NT) emnext = em[(t + 1) * NT + j];
            if (j < NT) {
                float bb4[4] = {-1e30f, -1e30f, -1e30f, -1e30f};
                int   bi4[4] = {0, 9, 18, 27};
#pragma unroll
                for (int c4 = 0; c4 < 4; c4++) {
#pragma unroll
                    for (int k = 0; k < 9; k++) {
                        int i = c4 * 9 + k;
                        float v = buf[prev][i] + Tcol[i];
                        if (v > bb4[c4]) { bb4[c4] = v; bi4[c4] = i; }
                    }
                }
                float best = bb4[0]; int bi = bi4[0];
                if (bb4[1] > best) { best = bb4[1]; bi = bi4[1]; }
                if (bb4[2] > best) { best = bb4[2]; bi = bi4[2]; }
                if (bb4[3] > best) { best = bb4[3]; bi = bi4[3]; }
                buf[cur][j] = best + ec;
                bp[(t - 1) * NT + j] = (unsigned char)bi;
            }
            __syncthreads();
        }
        const int lastbuf = (xlen >= 2) ? ((xlen - 1) & 1) : 0;
        if (j < NT) red[j] = buf[lastbuf][j] + TjS;
        __syncthreads();
        if (tid == 0) {
            float bs = -1e30f; int lt = 0;
            for (int i = 0; i < NT; i++) {
                float v = red[i];
                if (v > bs) { bs = v; lt = i; }
            }
            out[1 + BB * SS + b] = bs;   // path_score
            sh_last = lt;
        }
        __syncthreads();

        float* op = out + 1 + b * SS;
        for (int s = xlen + tid; s < SS; s += 64) op[s] = 0.f;  // masked tail
        if (tid == 0 && xlen > 0) {
            int tag = sh_last;
            op[xlen - 1] = (float)tag;
            for (int t = xlen - 1; t >= 1; t--) {
                tag = bp[(t - 1) * NT + tag];
                op[t - 1] = (float)tag;
            }
        }
    }
}

// ---------------- Kernel 3: deterministic loss reduction ----------------
__global__ void finish_kernel(float* __restrict__ out) {
    if (threadIdx.x == 0 && blockIdx.x == 0) {
        float a = 0.f;
        for (int i = 0; i < BB; i++) a += g_lossb[i];
        out[0] = a;
    }
}

extern "C" void kernel_launch(void* const* d_in, const int* in_sizes, int n_in,
                              void* d_out, int out_size) {
    const float* x1    = (const float*)d_in[0];
    const int*   hidx  = (const int*)  d_in[1];
    const int*   tags  = (const int*)  d_in[2];
    const float* W     = (const float*)d_in[3];
    const float* bias  = (const float*)d_in[4];
    const float* trans = (const float*)d_in[5];
    float* out = (float*)d_out;

    gemm_kernel<<<256, 256>>>(x1, hidx, W, bias);   // 128 rows/block, K split 2-way
    scan_kernel<<<128, 64>>>(hidx, tags, trans, out);
    finish_kernel<<<1, 32>>>(out);
}

// round 6
// speedup vs baseline: 1.6441x; 1.0735x over previous
#include <cuda_runtime.h>
#include <math.h>

#define BB 64
#define SS 512
#define HH 768
#define NT 36
#define TSTART 34
#define TSTOP 35
#define KT 16          // k-tile
#define GEMM_BLOCKS 512
#define KQ 192         // K per quarter (768/4)

// Scratch (device globals — no allocation allowed)
__device__ float g_emit [BB * SS * NT];   // leaky_relu(x@W+b)
__device__ float g_eemit[BB * SS * NT];   // exp(emit)
__device__ float g_lossb[BB];
__device__ int   g_cnt  [BB];             // per-batch gemm-block completion counters

// ---------------- f32x2 helpers ----------------
__device__ __forceinline__ unsigned long long pack2(float a, float b) {
    unsigned long long r;
    asm("mov.b64 %0, {%1, %2};" : "=l"(r) : "f"(a), "f"(b));
    return r;
}
__device__ __forceinline__ void unpack2(unsigned long long v, float& a, float& b) {
    asm("mov.b64 {%0, %1}, %2;" : "=f"(a), "=f"(b) : "l"(v));
}
__device__ __forceinline__ unsigned long long fma2(unsigned long long a,
                                                   unsigned long long b,
                                                   unsigned long long c) {
    unsigned long long d;
    asm("fma.rn.f32x2 %0, %1, %2, %3;" : "=l"(d) : "l"(a), "l"(b), "l"(c));
    return d;
}
__device__ __forceinline__ unsigned long long add2(unsigned long long a,
                                                   unsigned long long b) {
    unsigned long long d;
    asm("add.rn.f32x2 %0, %1, %2;" : "=l"(d) : "l"(a), "l"(b));
    return d;
}

// ---------------- init: zero flags (every replay) ----------------
__global__ void init_kernel() {
    if (threadIdx.x < BB) g_cnt[threadIdx.x] = 0;
}

// ---------------- fused kernel ----------------
// blocks [0,512):   gather + GEMM (64 rows/block, K split 4-way) + leaky + exp
// blocks [512,576): NLL scan for batch (bid-512), spins on g_cnt
// blocks [576,640): Viterbi for batch (bid-576), spins on g_cnt
__global__ __launch_bounds__(256, 3) void fused_kernel(
    const float* __restrict__ x1, const int* __restrict__ hidx,
    const float* __restrict__ W, const float* __restrict__ bias,
    const int* __restrict__ tags, const float* __restrict__ trans,
    float* __restrict__ out)
{
    __shared__ __align__(16) union {
        struct { float Xs[4][64][KT + 1]; float Ws[4][KT][36]; } g;  // 26624 B
        float part[3][64][37];                                       // 28416 B
        char  uu[(SS - 1) * NT];                                     // 18396 B (Tsh / bp)
    } u;
    __shared__ int   src[64];
    __shared__ __align__(16) float buf[2][NT];
    __shared__ float red[64];
    __shared__ int   ired[64];
    __shared__ int   sh_xlen, sh_last;

    const int tid = threadIdx.x;
    const int bid = blockIdx.x;

    if (bid < GEMM_BLOCKS) {
        // ================= GEMM =================
        const int q = tid >> 6;        // K quarter
        const int r = tid & 63;        // row within block
        const int rowbase = bid * 64;

        if (tid < 64) {
            int g = rowbase + tid;
            int b = g >> 9;
            src[tid] = (b << 9) * HH + hidx[g] * HH;
        }

        unsigned long long acc[18];
#pragma unroll
        for (int p = 0; p < 18; p++) acc[p] = 0ull;

        __syncthreads();

        const int kbase = q * KQ;
        for (int kt = 0; kt < KQ / KT; kt++) {
            const int k0 = kbase + kt * KT;
            // W tile: KT*36 = 576 floats per quarter, 64 threads
            float* wf = &u.g.Ws[q][0][0];
#pragma unroll
            for (int it = 0; it < 9; it++)
                wf[r + it * 64] = W[k0 * 36 + r + it * 64];
            // X tile: 64 rows x KT floats per quarter
#pragma unroll
            for (int it = 0; it < 16; it++) {
                int idx = r + it * 64;
                int rr = idx >> 4, kk = idx & 15;
                u.g.Xs[q][rr][kk] = x1[src[rr] + k0 + kk];
            }
            __syncthreads();

#pragma unroll
            for (int kk = 0; kk < KT; kk++) {
                float x = u.g.Xs[q][r][kk];
                unsigned long long xx = pack2(x, x);
                const ulonglong2* wrow =
                    reinterpret_cast<const ulonglong2*>(&u.g.Ws[q][kk][0]);
#pragma unroll
                for (int p = 0; p < 9; p++) {
                    ulonglong2 w = wrow[p];                 // LDS.128 broadcast
                    acc[2 * p]     = fma2(xx, w.x, acc[2 * p]);
                    acc[2 * p + 1] = fma2(xx, w.y, acc[2 * p + 1]);
                }
            }
            __syncthreads();
        }

        // unpack accumulators
        float av[36];
#pragma unroll
        for (int p = 0; p < 9; p++) {
            unpack2(acc[2 * p],     av[4 * p],     av[4 * p + 1]);
            unpack2(acc[2 * p + 1], av[4 * p + 2], av[4 * p + 3]);
        }

        if (q != 0) {
#pragma unroll
            for (int c = 0; c < 36; c++) u.part[q - 1][r][c] = av[c];
        }
        __syncthreads();

        if (q == 0) {
            const long long row = rowbase + r;
            float ev[36], eev[36];
#pragma unroll
            for (int c = 0; c < 36; c++) {
                float v = av[c] + u.part[0][r][c] + u.part[1][r][c] +
                          u.part[2][r][c] + bias[c];
                v = (v >= 0.f) ? v : 0.01f * v;
                ev[c] = v;
                eev[c] = __expf(v);
            }
            float4* pe  = reinterpret_cast<float4*>(g_emit  + row * 36);
            float4* pee = reinterpret_cast<float4*>(g_eemit + row * 36);
#pragma unroll
            for (int c4 = 0; c4 < 9; c4++) {
                pe[c4]  = make_float4(ev[4*c4],  ev[4*c4+1],  ev[4*c4+2],  ev[4*c4+3]);
                pee[c4] = make_float4(eev[4*c4], eev[4*c4+1], eev[4*c4+2], eev[4*c4+3]);
            }
        }
        __syncthreads();
        if (tid == 0) {
            __threadfence();
            atomicAdd(&g_cnt[rowbase >> 9], 1);
        }
        return;
    }

    // ================= SCANS =================
    const int sb = bid - GEMM_BLOCKS;
    const int b  = sb & 63;
    const bool viterbi = (sb >= BB);
    const int j = tid;

    // xlen = max(head_indexes[b, :])
    if (tid < 64) {
        int lm = 0;
        for (int s = tid; s < SS; s += 64) lm = max(lm, hidx[b * SS + s]);
        ired[tid] = lm;
    }
    __syncthreads();
    if (tid == 0) {
        int m = 0;
        for (int i = 0; i < 64; i++) m = max(m, ired[i]);
        sh_xlen = m;
    }
    __syncthreads();
    const int xlen = sh_xlen;

    if (!viterbi) {
        // ---------------- NLL (scaled forward) ----------------
        float* Tsh = reinterpret_cast<float*>(u.uu);
        for (int i = tid; i < NT * NT; i += 256) Tsh[i] = trans[i];
        __syncthreads();

        unsigned long long Ecol2[18];
        float Cl = 0.f;
        if (j < NT) {
#pragma unroll
            for (int p = 0; p < 18; p++)
                Ecol2[p] = pack2(__expf(Tsh[(2 * p) * NT + j]),
                                 __expf(Tsh[(2 * p + 1) * NT + j]));
        }

        // wait for this batch's emissions
        if (tid == 0) {
            volatile int* c = &g_cnt[b];
            while (*c < 8) __nanosleep(128);
            __threadfence();
        }
        __syncthreads();

        if (j < NT)
            buf[0][j] = __expf(g_emit[(b * SS) * NT + j] + Tsh[TSTART * NT + j]);
        __syncthreads();

        const float* ee = g_eemit + (long long)b * SS * NT;
        float eenext = (xlen > 1 && j < NT) ? ee[NT + j] : 0.f;
        for (int t = 1; t < xlen; t++) {
            const int cur = t & 1, prev = cur ^ 1;
            float eecur = eenext;
            if (t + 1 < xlen && j < NT) eenext = ee[(t + 1) * NT + j];
            if (j < NT) {
                const unsigned long long* vp =
                    reinterpret_cast<const unsigned long long*>(&buf[prev][0]);
                unsigned long long c0 = 0, c1 = 0, c2 = 0, c3 = 0;
                float m0 = 0.f, m1 = 0.f, m2 = 0.f, m3 = 0.f;
#pragma unroll
                for (int p = 0; p < 16; p += 4) {
                    unsigned long long v0 = vp[p], v1 = vp[p+1], v2 = vp[p+2], v3 = vp[p+3];
                    c0 = fma2(v0, Ecol2[p],   c0);
                    c1 = fma2(v1, Ecol2[p+1], c1);
                    c2 = fma2(v2, Ecol2[p+2], c2);
                    c3 = fma2(v3, Ecol2[p+3], c3);
                    float a, bb2;
                    unpack2(v0, a, bb2); m0 = fmaxf(m0, fmaxf(a, bb2));
                    unpack2(v1, a, bb2); m1 = fmaxf(m1, fmaxf(a, bb2));
                    unpack2(v2, a, bb2); m2 = fmaxf(m2, fmaxf(a, bb2));
                    unpack2(v3, a, bb2); m3 = fmaxf(m3, fmaxf(a, bb2));
                }
                {
                    unsigned long long v0 = vp[16], v1 = vp[17];
                    c0 = fma2(v0, Ecol2[16], c0);
                    c1 = fma2(v1, Ecol2[17], c1);
                    float a, bb2;
                    unpack2(v0, a, bb2); m0 = fmaxf(m0, fmaxf(a, bb2));
                    unpack2(v1, a, bb2); m1 = fmaxf(m1, fmaxf(a, bb2));
                }
                unsigned long long cs = add2(add2(c0, c1), add2(c2, c3));
                float sa, sbv; unpack2(cs, sa, sbv);
                float accv = sa + sbv;
                float m = fmaxf(fmaxf(m0, m1), fmaxf(m2, m3));
                buf[cur][j] = accv * (1.0f / m) * eecur;
                Cl += __logf(m);
            }
            __syncthreads();
        }
        const int lastbuf = (xlen >= 2) ? ((xlen - 1) & 1) : 0;
        if (j < NT) red[j] = buf[lastbuf][j] * __expf(Tsh[j * NT + TSTOP]);
        __syncthreads();

        float logZ = 0.f;
        if (tid == 0) {
            float sZ = 0.f;
            for (int i = 0; i < NT; i++) sZ += red[i];
            logZ = Cl + __logf(sZ);
        }
        __syncthreads();

        // gold score
        const int* tg = tags + b * SS;
        if (tid < 64) {
            float gp = 0.f;
            for (int s = tid; s < xlen; s += 64) {
                int cs = tg[s];
                gp += g_emit[((long long)b * SS + s) * NT + cs];
                if (s >= 1) gp += Tsh[tg[s - 1] * NT + cs];
            }
            red[tid] = gp;
        }
        __syncthreads();
        if (tid == 0) {
            float g = 0.f;
            for (int i = 0; i < 64; i++) g += red[i];
            int li = (xlen > 0) ? (xlen - 1) : 0;
            g += Tsh[TSTART * NT + tg[0]] + Tsh[tg[li] * NT + TSTOP];
            g_lossb[b] = logZ - g;
        }
    } else {
        // ---------------- Viterbi ----------------
        unsigned char* bp = reinterpret_cast<unsigned char*>(u.uu);
        float Tcol[NT];
        float TjS = 0.f;
        if (j < NT) {
#pragma unroll
            for (int i = 0; i < NT; i++) Tcol[i] = trans[i * NT + j];
            TjS = trans[j * NT + TSTOP];
        }

        if (tid == 0) {
            volatile int* c = &g_cnt[b];
            while (*c < 8) __nanosleep(128);
            __threadfence();
        }
        __syncthreads();

        if (j < NT)
            buf[0][j] = g_emit[(b * SS) * NT + j] + trans[TSTART * NT + j];
        __syncthreads();

        const float* em = g_emit + (long long)b * SS * NT;
        float emnext = (xlen > 1 && j < NT) ? em[NT + j] : 0.f;
        for (int t = 1; t < xlen; t++) {
            const int cur = t & 1, prev = cur ^ 1;
            float ec = emnext;
            if (t + 1 < xlen && j < NT) emnext = em[(t + 1) * NT + j];
            if (j < NT) {
                float bb4[4] = {-1e30f, -1e30f, -1e30f, -1e30f};
                int   bi4[4] = {0, 9, 18, 27};
#pragma unroll
                for (int c4 = 0; c4 < 4; c4++) {
#pragma unroll
                    for (int k = 0; k < 9; k++) {
                        int i = c4 * 9 + k;
                        float v = buf[prev][i] + Tcol[i];
                        bool gt = v > bb4[c4];
                        bb4[c4] = gt ? v : bb4[c4];
                        bi4[c4] = gt ? i : bi4[c4];
                    }
                }
                float best = bb4[0]; int bi = bi4[0];
                if (bb4[1] > best) { best = bb4[1]; bi = bi4[1]; }
                if (bb4[2] > best) { best = bb4[2]; bi = bi4[2]; }
                if (bb4[3] > best) { best = bb4[3]; bi = bi4[3]; }
                buf[cur][j] = best + ec;
                bp[(t - 1) * NT + j] = (unsigned char)bi;
            }
            __syncthreads();
        }
        const int lastbuf = (xlen >= 2) ? ((xlen - 1) & 1) : 0;
        if (j < NT) red[j] = buf[lastbuf][j] + TjS;
        __syncthreads();
        if (tid == 0) {
            float bs = -1e30f; int lt = 0;
            for (int i = 0; i < NT; i++) {
                float v = red[i];
                if (v > bs) { bs = v; lt = i; }
            }
            out[1 + BB * SS + b] = bs;   // path_score
            sh_last = lt;
        }
        __syncthreads();

        float* op = out + 1 + b * SS;
        for (int s = xlen + tid; s < SS; s += 256) op[s] = 0.f;  // masked tail
        if (tid == 0 && xlen > 0) {
            int tag = sh_last;
            op[xlen - 1] = (float)tag;
            for (int t = xlen - 1; t >= 1; t--) {
                tag = bp[(t - 1) * NT + tag];
                op[t - 1] = (float)tag;
            }
        }
    }
}

// ---------------- finish: deterministic loss reduction ----------------
__global__ void finish_kernel(float* __restrict__ out) {
    if (threadIdx.x == 0 && blockIdx.x == 0) {
        float a = 0.f;
        for (int i = 0; i < BB; i++) a += g_lossb[i];
        out[0] = a;
    }
}

extern "C" void kernel_launch(void* const* d_in, const int* in_sizes, int n_in,
                              void* d_out, int out_size) {
    const float* x1    = (const float*)d_in[0];
    const int*   hidx  = (const int*)  d_in[1];
    const int*   tags  = (const int*)  d_in[2];
    const float* W     = (const float*)d_in[3];
    const float* bias  = (const float*)d_in[4];
    const float* trans = (const float*)d_in[5];
    float* out = (float*)d_out;

    init_kernel<<<1, 64>>>();
    fused_kernel<<<GEMM_BLOCKS + 128, 256>>>(x1, hidx, W, bias, tags, trans, out);
    finish_kernel<<<1, 32>>>(out);
}

// round 7
// speedup vs baseline: 1.8576x; 1.1299x over previous
#include <cuda_runtime.h>
#include <math.h>

#define BB 64
#define SS 512
#define HH 768
#define NT 36
#define TSTART 34
#define TSTOP 35
#define KT 16            // k-tile
#define KQ 192           // K per quarter (768/4)
#define SCAN_BLOCKS 128
#define GEMM_BLOCKS 512

// Scratch (device globals — no allocation allowed)
__device__ float g_emit [BB * SS * NT];   // leaky_relu(x@W+b)
__device__ float g_eemit[BB * SS * NT];   // exp(emit)
__device__ float g_lossb[BB];
__device__ int   g_done [BB * 8];         // per-(batch,chunk) readiness flags

// ---------------- f32x2 helpers ----------------
__device__ __forceinline__ unsigned long long pack2(float a, float b) {
    unsigned long long r;
    asm("mov.b64 %0, {%1, %2};" : "=l"(r) : "f"(a), "f"(b));
    return r;
}
__device__ __forceinline__ void unpack2(unsigned long long v, float& a, float& b) {
    asm("mov.b64 {%0, %1}, %2;" : "=f"(a), "=f"(b) : "l"(v));
}
__device__ __forceinline__ unsigned long long fma2(unsigned long long a,
                                                   unsigned long long b,
                                                   unsigned long long c) {
    unsigned long long d;
    asm("fma.rn.f32x2 %0, %1, %2, %3;" : "=l"(d) : "l"(a), "l"(b), "l"(c));
    return d;
}
__device__ __forceinline__ unsigned long long add2(unsigned long long a,
                                                   unsigned long long b) {
    unsigned long long d;
    asm("add.rn.f32x2 %0, %1, %2;" : "=l"(d) : "l"(a), "l"(b));
    return d;
}
__device__ __forceinline__ void barr64() {
    asm volatile("bar.sync 0, 64;" ::: "memory");
}
__device__ __forceinline__ void wait_flag(int idx) {
    volatile int* f = &g_done[idx];
    while (*f == 0) __nanosleep(64);
}

// ---------------- init: zero flags (every replay) ----------------
__global__ void init_kernel() {
    int i = threadIdx.x + blockIdx.x * blockDim.x;
    if (i < BB * 8) g_done[i] = 0;
}

// ---------------- fused kernel ----------------
// blocks [0,64):    NLL scan for batch bid        (spins on per-chunk flags)
// blocks [64,128):  Viterbi for batch bid-64      (spins on per-chunk flags)
// blocks [128,640): gather+GEMM, chunk-major: c=(bid-128)>>6, b=(bid-128)&63
__global__ __launch_bounds__(256, 3) void fused_kernel(
    const float* __restrict__ x1, const int* __restrict__ hidx,
    const float* __restrict__ W, const float* __restrict__ bias,
    const int* __restrict__ tags, const float* __restrict__ trans,
    float* __restrict__ out)
{
    __shared__ __align__(16) union {
        float Xs[2][4][64][17];        // 34816 B (double-buffered X tiles)
        float part[3][64][37];         // 28416 B (quarter partials)
        char  uu[(SS - 1) * NT];       // 18396 B (Tsh / backpointers)
    } u;
    __shared__ int   src[64];
    __shared__ __align__(16) float buf[2][NT];
    __shared__ float red[64];
    __shared__ int   ired[64];
    __shared__ int   sh_xlen, sh_last;

    const int tid = threadIdx.x;
    const int bid = blockIdx.x;

    if (bid >= SCAN_BLOCKS) {
        // ================= GEMM =================
        const int gb = bid - SCAN_BLOCKS;
        const int c  = gb >> 6;          // seq chunk 0..7
        const int b  = gb & 63;          // batch
        const int rowbase = b * SS + c * 64;
        const int q = tid >> 6;          // K quarter
        const int r = tid & 63;          // row within block

        if (tid < 64) {
            int g = rowbase + tid;
            src[tid] = (b << 9) * HH + hidx[g] * HH;
        }

        unsigned long long acc[18];
#pragma unroll
        for (int p = 0; p < 18; p++) acc[p] = 0ull;

        __syncthreads();

        const int kbase = q * KQ;
        const longlong2* W2 = reinterpret_cast<const longlong2*>(W);

        // stage tile 0
        {
            const int k0 = kbase;
#pragma unroll
            for (int it = 0; it < 4; it++) {
                int idx = r + it * 64;
                int rr = idx >> 2, c4 = idx & 3;
                const float4* xp = reinterpret_cast<const float4*>(x1 + src[rr] + k0);
                float4 v = __ldcg(xp + c4);
                float* d = &u.Xs[0][q][rr][c4 * 4];
                d[0] = v.x; d[1] = v.y; d[2] = v.z; d[3] = v.w;
            }
        }
        __syncthreads();

        for (int kt = 0; kt < KQ / KT; kt++) {
            const int bb = kt & 1;
            // prefetch next tile into other buffer
            if (kt + 1 < KQ / KT) {
                const int k0n = kbase + (kt + 1) * KT;
#pragma unroll
                for (int it = 0; it < 4; it++) {
                    int idx = r + it * 64;
                    int rr = idx >> 2, c4 = idx & 3;
                    const float4* xp = reinterpret_cast<const float4*>(x1 + src[rr] + k0n);
                    float4 v = __ldcg(xp + c4);
                    float* d = &u.Xs[bb ^ 1][q][rr][c4 * 4];
                    d[0] = v.x; d[1] = v.y; d[2] = v.z; d[3] = v.w;
                }
            }
            // compute current tile; W direct from global (L1-resident, uniform LDG.128)
            const int k0 = kbase + kt * KT;
#pragma unroll
            for (int kk = 0; kk < KT; kk++) {
                float x = u.Xs[bb][q][r][kk];
                unsigned long long xx = pack2(x, x);
                const longlong2* wrow = W2 + (k0 + kk) * 9;
#pragma unroll
                for (int p = 0; p < 9; p++) {
                    longlong2 w = __ldg(wrow + p);
                    acc[2 * p]     = fma2(xx, (unsigned long long)w.x, acc[2 * p]);
                    acc[2 * p + 1] = fma2(xx, (unsigned long long)w.y, acc[2 * p + 1]);
                }
            }
            __syncthreads();
        }

        // unpack accumulators
        float av[36];
#pragma unroll
        for (int p = 0; p < 9; p++) {
            unpack2(acc[2 * p],     av[4 * p],     av[4 * p + 1]);
            unpack2(acc[2 * p + 1], av[4 * p + 2], av[4 * p + 3]);
        }

        if (q != 0) {
#pragma unroll
            for (int cc = 0; cc < 36; cc++) u.part[q - 1][r][cc] = av[cc];
        }
        __syncthreads();

        if (q == 0) {
            const long long row = rowbase + r;
            float ev[36], eev[36];
#pragma unroll
            for (int cc = 0; cc < 36; cc++) {
                float v = av[cc] + u.part[0][r][cc] + u.part[1][r][cc] +
                          u.part[2][r][cc] + bias[cc];
                v = (v >= 0.f) ? v : 0.01f * v;
                ev[cc] = v;
                eev[cc] = __expf(v);
            }
            float4* pe  = reinterpret_cast<float4*>(g_emit  + row * 36);
            float4* pee = reinterpret_cast<float4*>(g_eemit + row * 36);
#pragma unroll
            for (int c4 = 0; c4 < 9; c4++) {
                pe[c4]  = make_float4(ev[4*c4],  ev[4*c4+1],  ev[4*c4+2],  ev[4*c4+3]);
                pee[c4] = make_float4(eev[4*c4], eev[4*c4+1], eev[4*c4+2], eev[4*c4+3]);
            }
        }
        __syncthreads();
        if (tid == 0) {
            __threadfence();
            atomicExch(&g_done[b * 8 + c], 1);
        }
        return;
    }

    // ================= SCANS (threads 0-63 only) =================
    if (tid >= 64) return;

    const int b = bid & 63;
    const bool viterbi = (bid >= BB);
    const int j = tid;

    // xlen = max(head_indexes[b, :])
    {
        int lm = 0;
        for (int s = tid; s < SS; s += 64) lm = max(lm, hidx[b * SS + s]);
        ired[tid] = lm;
        barr64();
        if (tid == 0) {
            int m = 0;
            for (int i = 0; i < 64; i++) m = max(m, ired[i]);
            sh_xlen = m;
        }
        barr64();
    }
    const int xlen = sh_xlen;
    const int cmax = (xlen - 1) >> 6;   // last chunk holding rows < xlen (xlen>=1)
    int sready = 0;                      // thread-0's waited-chunk counter

    if (!viterbi) {
        // ---------------- NLL (scaled forward) ----------------
        float* Tsh = reinterpret_cast<float*>(u.uu);
        for (int i = tid; i < NT * NT; i += 64) Tsh[i] = trans[i];
        barr64();

        unsigned long long Ecol2[18];
        float Cl = 0.f;
        if (j < NT) {
#pragma unroll
            for (int p = 0; p < 18; p++)
                Ecol2[p] = pack2(__expf(Tsh[(2 * p) * NT + j]),
                                 __expf(Tsh[(2 * p + 1) * NT + j]));
        }

        // wait chunk 0 (row 0 + row 1 prefetch)
        if (tid == 0) { wait_flag(b * 8 + 0); sready = 1; __threadfence(); }
        barr64();

        if (j < NT)
            buf[0][j] = __expf(g_emit[(b * SS) * NT + j] + Tsh[TSTART * NT + j]);
        barr64();

        const float* ee = g_eemit + (long long)b * SS * NT;
        float eenext = (xlen > 1 && j < NT) ? ee[NT + j] : 0.f;
        int t = 1;
        for (int c = 0; c <= cmax; c++) {
            const int wc = min(c + 1, cmax);
            if (tid == 0) {
                for (; sready <= wc; sready++) wait_flag(b * 8 + sready);
                __threadfence();
            }
            barr64();
            const int tend = min((c + 1) * 64, xlen);
            for (; t < tend; t++) {
                const int cur = t & 1, prev = cur ^ 1;
                float eecur = eenext;
                if (t + 1 < xlen && j < NT) eenext = ee[(t + 1) * NT + j];
                if (j < NT) {
                    const unsigned long long* vp =
                        reinterpret_cast<const unsigned long long*>(&buf[prev][0]);
                    unsigned long long c0 = 0, c1 = 0, c2 = 0, c3 = 0;
                    float m0 = 0.f, m1 = 0.f, m2 = 0.f, m3 = 0.f;
#pragma unroll
                    for (int p = 0; p < 16; p += 4) {
                        unsigned long long v0 = vp[p], v1 = vp[p+1], v2 = vp[p+2], v3 = vp[p+3];
                        c0 = fma2(v0, Ecol2[p],   c0);
                        c1 = fma2(v1, Ecol2[p+1], c1);
                        c2 = fma2(v2, Ecol2[p+2], c2);
                        c3 = fma2(v3, Ecol2[p+3], c3);
                        float a, bb2;
                        unpack2(v0, a, bb2); m0 = fmaxf(m0, fmaxf(a, bb2));
                        unpack2(v1, a, bb2); m1 = fmaxf(m1, fmaxf(a, bb2));
                        unpack2(v2, a, bb2); m2 = fmaxf(m2, fmaxf(a, bb2));
                        unpack2(v3, a, bb2); m3 = fmaxf(m3, fmaxf(a, bb2));
                    }
                    {
                        unsigned long long v0 = vp[16], v1 = vp[17];
                        c0 = fma2(v0, Ecol2[16], c0);
                        c1 = fma2(v1, Ecol2[17], c1);
                        float a, bb2;
                        unpack2(v0, a, bb2); m0 = fmaxf(m0, fmaxf(a, bb2));
                        unpack2(v1, a, bb2); m1 = fmaxf(m1, fmaxf(a, bb2));
                    }
                    unsigned long long cs = add2(add2(c0, c1), add2(c2, c3));
                    float sa, sbv; unpack2(cs, sa, sbv);
                    float accv = sa + sbv;
                    float m = fmaxf(fmaxf(m0, m1), fmaxf(m2, m3));
                    buf[cur][j] = accv * (1.0f / m) * eecur;
                    Cl += __logf(m);
                }
                barr64();
            }
        }
        const int lastbuf = (xlen >= 2) ? ((xlen - 1) & 1) : 0;
        if (j < NT) red[j] = buf[lastbuf][j] * __expf(Tsh[j * NT + TSTOP]);
        barr64();

        float logZ = 0.f;
        if (tid == 0) {
            float sZ = 0.f;
            for (int i = 0; i < NT; i++) sZ += red[i];
            logZ = Cl + __logf(sZ);
        }
        barr64();

        // gold score (all needed chunks already flagged)
        const int* tg = tags + b * SS;
        {
            float gp = 0.f;
            for (int s = tid; s < xlen; s += 64) {
                int cs = tg[s];
                gp += g_emit[((long long)b * SS + s) * NT + cs];
                if (s >= 1) gp += Tsh[tg[s - 1] * NT + cs];
            }
            red[tid] = gp;
        }
        barr64();
        if (tid == 0) {
            float g = 0.f;
            for (int i = 0; i < 64; i++) g += red[i];
            int li = (xlen > 0) ? (xlen - 1) : 0;
            g += Tsh[TSTART * NT + tg[0]] + Tsh[tg[li] * NT + TSTOP];
            g_lossb[b] = logZ - g;
        }
    } else {
        // ---------------- Viterbi ----------------
        unsigned char* bp = reinterpret_cast<unsigned char*>(u.uu);
        float Tcol[NT];
        float TjS = 0.f;
        if (j < NT) {
#pragma unroll
            for (int i = 0; i < NT; i++) Tcol[i] = trans[i * NT + j];
            TjS = trans[j * NT + TSTOP];
        }

        if (tid == 0) { wait_flag(b * 8 + 0); sready = 1; __threadfence(); }
        barr64();

        if (j < NT)
            buf[0][j] = g_emit[(b * SS) * NT + j] + trans[TSTART * NT + j];
        barr64();

        const float* em = g_emit + (long long)b * SS * NT;
        float emnext = (xlen > 1 && j < NT) ? em[NT + j] : 0.f;
        int t = 1;
        for (int c = 0; c <= cmax; c++) {
            const int wc = min(c + 1, cmax);
            if (tid == 0) {
                for (; sready <= wc; sready++) wait_flag(b * 8 + sready);
                __threadfence();
            }
            barr64();
            const int tend = min((c + 1) * 64, xlen);
            for (; t < tend; t++) {
                const int cur = t & 1, prev = cur ^ 1;
                float ec = emnext;
                if (t + 1 < xlen && j < NT) emnext = em[(t + 1) * NT + j];
                if (j < NT) {
                    float bb4[4] = {-1e30f, -1e30f, -1e30f, -1e30f};
                    int   bi4[4] = {0, 9, 18, 27};
#pragma unroll
                    for (int c4 = 0; c4 < 4; c4++) {
#pragma unroll
                        for (int k = 0; k < 9; k++) {
                            int i = c4 * 9 + k;
                            float v = buf[prev][i] + Tcol[i];
                            bool gt = v > bb4[c4];
                            bb4[c4] = gt ? v : bb4[c4];
                            bi4[c4] = gt ? i : bi4[c4];
                        }
                    }
                    float best = bb4[0]; int bi = bi4[0];
                    if (bb4[1] > best) { best = bb4[1]; bi = bi4[1]; }
                    if (bb4[2] > best) { best = bb4[2]; bi = bi4[2]; }
                    if (bb4[3] > best) { best = bb4[3]; bi = bi4[3]; }
                    buf[cur][j] = best + ec;
                    bp[(t - 1) * NT + j] = (unsigned char)bi;
                }
                barr64();
            }
        }
        const int lastbuf = (xlen >= 2) ? ((xlen - 1) & 1) : 0;
        if (j < NT) red[j] = buf[lastbuf][j] + TjS;
        barr64();
        if (tid == 0) {
            float bs = -1e30f; int lt = 0;
            for (int i = 0; i < NT; i++) {
                float v = red[i];
                if (v > bs) { bs = v; lt = i; }
            }
            out[1 + BB * SS + b] = bs;   // path_score
            sh_last = lt;
        }
        barr64();

        float* op = out + 1 + b * SS;
        for (int s = xlen + tid; s < SS; s += 64) op[s] = 0.f;  // masked tail
        if (tid == 0 && xlen > 0) {
            int tag = sh_last;
            op[xlen - 1] = (float)tag;
            for (int t2 = xlen - 1; t2 >= 1; t2--) {
                tag = bp[(t2 - 1) * NT + tag];
                op[t2 - 1] = (float)tag;
            }
        }
    }
}

// ---------------- finish: deterministic loss reduction ----------------
__global__ void finish_kernel(float* __restrict__ out) {
    if (threadIdx.x == 0 && blockIdx.x == 0) {
        float a = 0.f;
        for (int i = 0; i < BB; i++) a += g_lossb[i];
        out[0] = a;
    }
}

extern "C" void kernel_launch(void* const* d_in, const int* in_sizes, int n_in,
                              void* d_out, int out_size) {
    const float* x1    = (const float*)d_in[0];
    const int*   hidx  = (const int*)  d_in[1];
    const int*   tags  = (const int*)  d_in[2];
    const float* W     = (const float*)d_in[3];
    const float* bias  = (const float*)d_in[4];
    const float* trans = (const float*)d_in[5];
    float* out = (float*)d_out;

    init_kernel<<<2, 256>>>();
    fused_kernel<<<SCAN_BLOCKS + GEMM_BLOCKS, 256>>>(x1, hidx, W, bias, tags, trans, out);
    finish_kernel<<<1, 32>>>(out);
}

// round 8
// speedup vs baseline: 1.9192x; 1.0332x over previous
#include <cuda_runtime.h>
#include <math.h>

#define BB 64
#define SS 512
#define HH 768
#define NT 36
#define TSTART 34
#define TSTOP 35
#define KQ 192           // K per quarter (768/4)
#define SCAN_BLOCKS 128
#define GEMM_BLOCKS 512

// Scratch (device globals — no allocation allowed)
__device__ float g_emit [BB * SS * NT];   // leaky_relu(x@W+b)
__device__ float g_eemit[BB * SS * NT];   // exp(emit)
__device__ float g_lossb[BB];
__device__ int   g_done [BB * 8];         // per-(batch,chunk) readiness flags
__device__ int   g_nllcnt;                // NLL-block completion counter

// ---------------- f32x2 helpers ----------------
__device__ __forceinline__ unsigned long long pack2(float a, float b) {
    unsigned long long r;
    asm("mov.b64 %0, {%1, %2};" : "=l"(r) : "f"(a), "f"(b));
    return r;
}
__device__ __forceinline__ void unpack2(unsigned long long v, float& a, float& b) {
    asm("mov.b64 {%0, %1}, %2;" : "=f"(a), "=f"(b) : "l"(v));
}
__device__ __forceinline__ unsigned long long fma2(unsigned long long a,
                                                   unsigned long long b,
                                                   unsigned long long c) {
    unsigned long long d;
    asm("fma.rn.f32x2 %0, %1, %2, %3;" : "=l"(d) : "l"(a), "l"(b), "l"(c));
    return d;
}
__device__ __forceinline__ unsigned long long add2(unsigned long long a,
                                                   unsigned long long b) {
    unsigned long long d;
    asm("add.rn.f32x2 %0, %1, %2;" : "=l"(d) : "l"(a), "l"(b));
    return d;
}
__device__ __forceinline__ void barr64() {
    asm volatile("bar.sync 0, 64;" ::: "memory");
}
__device__ __forceinline__ void wait_flag(int idx) {
    volatile int* f = &g_done[idx];
    while (*f == 0) __nanosleep(64);
}

// ---------------- init: zero flags (every replay) ----------------
__global__ void init_kernel() {
    int i = threadIdx.x + blockIdx.x * blockDim.x;
    if (i < BB * 8) g_done[i] = 0;
    if (i == 0) g_nllcnt = 0;
}

// ---------------- fused kernel ----------------
// blocks [0,64):    NLL scan for batch bid        (spins on per-chunk flags)
// blocks [64,128):  Viterbi for batch bid-64      (spins on per-chunk flags)
// blocks [128,640): gather+GEMM, chunk-major: c=(bid-128)>>6, b=(bid-128)&63
// block  640:       loss reducer (spins on g_nllcnt)
__global__ __launch_bounds__(128, 4) void fused_kernel(
    const float* __restrict__ x1, const int* __restrict__ hidx,
    const float* __restrict__ W, const float* __restrict__ bias,
    const int* __restrict__ tags, const float* __restrict__ trans,
    float* __restrict__ out)
{
    __shared__ __align__(16) union {
        float Xs[4][16][66];           // 16896 B (k-major X tiles, conflict-free)
        float part[3][64][37];         // 28416 B (quarter partials)
        char  uu[(SS - 1) * NT];       // 18396 B (Tsh / backpointers)
    } u;
    __shared__ int   src[64];
    __shared__ __align__(16) float buf[2][NT];
    __shared__ float red[64];
    __shared__ int   ired[64];
    __shared__ int   sh_xlen, sh_last;

    const int tid = threadIdx.x;
    const int bid = blockIdx.x;

    if (bid >= SCAN_BLOCKS && bid < SCAN_BLOCKS + GEMM_BLOCKS) {
        // ================= GEMM (2 rows/thread) =================
        const int gb = bid - SCAN_BLOCKS;
        const int c  = gb >> 6;          // seq chunk 0..7
        const int b  = gb & 63;          // batch
        const int rowbase = b * SS + c * 64;
        const int q = tid >> 5;          // K quarter (one warp per quarter)
        const int r = tid & 31;          // lane -> rows r and r+32

        if (tid < 64) {
            int g = rowbase + tid;
            src[tid] = (b << 9) * HH + hidx[g] * HH;
        }

        unsigned long long acc[36];
#pragma unroll
        for (int p = 0; p < 36; p++) acc[p] = 0ull;

        __syncthreads();

        const int kbase = q * KQ;
        const longlong2* W2 = reinterpret_cast<const longlong2*>(W);

        for (int kt = 0; kt < KQ / 16; kt++) {
            const int k0 = kbase + kt * 16;
            // stage 64 rows x 16 k, transposed to k-major; 8 float4/thread
#pragma unroll
            for (int it = 0; it < 8; it++) {
                int idx = r + it * 32;
                int rr = idx >> 2, c4 = idx & 3;
                const float4* xp =
                    reinterpret_cast<const float4*>(x1 + src[rr] + k0);
                float4 v = __ldcg(xp + c4);
                u.Xs[q][c4 * 4 + 0][rr] = v.x;
                u.Xs[q][c4 * 4 + 1][rr] = v.y;
                u.Xs[q][c4 * 4 + 2][rr] = v.z;
                u.Xs[q][c4 * 4 + 3][rr] = v.w;
            }
            __syncthreads();

#pragma unroll
            for (int kk = 0; kk < 16; kk++) {
                float xa = u.Xs[q][kk][r];
                float xb = u.Xs[q][kk][r + 32];
                unsigned long long pa = pack2(xa, xa);
                unsigned long long pb = pack2(xb, xb);
                const longlong2* wrow = W2 + (k0 + kk) * 9;
#pragma unroll
                for (int p = 0; p < 9; p++) {
                    longlong2 w = __ldg(wrow + p);     // uniform LDG.128, L1-hit
                    acc[2 * p]          = fma2(pa, (unsigned long long)w.x, acc[2 * p]);
                    acc[2 * p + 1]      = fma2(pa, (unsigned long long)w.y, acc[2 * p + 1]);
                    acc[18 + 2 * p]     = fma2(pb, (unsigned long long)w.x, acc[18 + 2 * p]);
                    acc[18 + 2 * p + 1] = fma2(pb, (unsigned long long)w.y, acc[18 + 2 * p + 1]);
                }
            }
            __syncthreads();
        }

        // unpack accumulators: a0 = row r, a1 = row r+32
        float a0[36], a1[36];
#pragma unroll
        for (int p = 0; p < 9; p++) {
            unpack2(acc[2 * p],          a0[4 * p],     a0[4 * p + 1]);
            unpack2(acc[2 * p + 1],      a0[4 * p + 2], a0[4 * p + 3]);
            unpack2(acc[18 + 2 * p],     a1[4 * p],     a1[4 * p + 1]);
            unpack2(acc[18 + 2 * p + 1], a1[4 * p + 2], a1[4 * p + 3]);
        }

        if (q != 0) {
#pragma unroll
            for (int cc = 0; cc < 36; cc++) {
                u.part[q - 1][r][cc]      = a0[cc];
                u.part[q - 1][r + 32][cc] = a1[cc];
            }
        }
        __syncthreads();

        if (q == 0) {
#pragma unroll
            for (int rowsel = 0; rowsel < 2; rowsel++) {
                const int rr = r + rowsel * 32;
                const float* av = rowsel ? a1 : a0;
                const long long row = rowbase + rr;
                float ev[36], eev[36];
#pragma unroll
                for (int cc = 0; cc < 36; cc++) {
                    float v = av[cc] + u.part[0][rr][cc] + u.part[1][rr][cc] +
                              u.part[2][rr][cc] + bias[cc];
                    v = (v >= 0.f) ? v : 0.01f * v;
                    ev[cc] = v;
                    eev[cc] = __expf(v);
                }
                float4* pe  = reinterpret_cast<float4*>(g_emit  + row * 36);
                float4* pee = reinterpret_cast<float4*>(g_eemit + row * 36);
#pragma unroll
                for (int c4 = 0; c4 < 9; c4++) {
                    pe[c4]  = make_float4(ev[4*c4],  ev[4*c4+1],  ev[4*c4+2],  ev[4*c4+3]);
                    pee[c4] = make_float4(eev[4*c4], eev[4*c4+1], eev[4*c4+2], eev[4*c4+3]);
                }
            }
        }
        __syncthreads();
        if (tid == 0) {
            __threadfence();
            atomicExch(&g_done[b * 8 + c], 1);
        }
        return;
    }

    if (bid >= SCAN_BLOCKS + GEMM_BLOCKS) {
        // ================= loss reducer =================
        if (tid == 0) {
            volatile int* c = &g_nllcnt;
            while (*c < BB) __nanosleep(256);
            __threadfence();
            float a = 0.f;
            for (int i = 0; i < BB; i++) a += g_lossb[i];
            out[0] = a;
        }
        return;
    }

    // ================= SCANS (threads 0-63 only) =================
    if (tid >= 64) return;

    const int b = bid & 63;
    const bool viterbi = (bid >= BB);
    const int j = tid;

    // xlen = max(head_indexes[b, :])
    {
        int lm = 0;
        for (int s = tid; s < SS; s += 64) lm = max(lm, hidx[b * SS + s]);
        ired[tid] = lm;
        barr64();
        if (tid == 0) {
            int m = 0;
            for (int i = 0; i < 64; i++) m = max(m, ired[i]);
            sh_xlen = m;
        }
        barr64();
    }
    const int xlen = sh_xlen;
    const int cmax = (xlen - 1) >> 6;
    int sready = 0;

    if (!viterbi) {
        // ---------------- NLL (scaled forward) ----------------
        float* Tsh = reinterpret_cast<float*>(u.uu);
        for (int i = tid; i < NT * NT; i += 64) Tsh[i] = trans[i];
        barr64();

        unsigned long long Ecol2[18];
        float Cl = 0.f;
        if (j < NT) {
#pragma unroll
            for (int p = 0; p < 18; p++)
                Ecol2[p] = pack2(__expf(Tsh[(2 * p) * NT + j]),
                                 __expf(Tsh[(2 * p + 1) * NT + j]));
        }

        if (tid == 0) { wait_flag(b * 8 + 0); sready = 1; __threadfence(); }
        barr64();

        if (j < NT)
            buf[0][j] = __expf(g_emit[(b * SS) * NT + j] + Tsh[TSTART * NT + j]);
        barr64();

        const float* ee = g_eemit + (long long)b * SS * NT;
        float eenext = (xlen > 1 && j < NT) ? ee[NT + j] : 0.f;
        int t = 1;
        for (int c = 0; c <= cmax; c++) {
            const int wc = min(c + 1, cmax);
            if (tid == 0) {
                for (; sready <= wc; sready++) wait_flag(b * 8 + sready);
                __threadfence();
            }
            barr64();
            const int tend = min((c + 1) * 64, xlen);
            for (; t < tend; t++) {
                const int cur = t & 1, prev = cur ^ 1;
                float eecur = eenext;
                if (t + 1 < xlen && j < NT) eenext = ee[(t + 1) * NT + j];
                if (j < NT) {
                    const unsigned long long* vp =
                        reinterpret_cast<const unsigned long long*>(&buf[prev][0]);
                    unsigned long long c0 = 0, c1 = 0, c2 = 0, c3 = 0;
                    float m0 = 0.f, m1 = 0.f, m2 = 0.f, m3 = 0.f;
#pragma unroll
                    for (int p = 0; p < 16; p += 4) {
                        unsigned long long v0 = vp[p], v1 = vp[p+1], v2 = vp[p+2], v3 = vp[p+3];
                        c0 = fma2(v0, Ecol2[p],   c0);
                        c1 = fma2(v1, Ecol2[p+1], c1);
                        c2 = fma2(v2, Ecol2[p+2], c2);
                        c3 = fma2(v3, Ecol2[p+3], c3);
                        float a, bb2;
                        unpack2(v0, a, bb2); m0 = fmaxf(m0, fmaxf(a, bb2));
                        unpack2(v1, a, bb2); m1 = fmaxf(m1, fmaxf(a, bb2));
                        unpack2(v2, a, bb2); m2 = fmaxf(m2, fmaxf(a, bb2));
                        unpack2(v3, a, bb2); m3 = fmaxf(m3, fmaxf(a, bb2));
                    }
                    {
                        unsigned long long v0 = vp[16], v1 = vp[17];
                        c0 = fma2(v0, Ecol2[16], c0);
                        c1 = fma2(v1, Ecol2[17], c1);
                        float a, bb2;
                        unpack2(v0, a, bb2); m0 = fmaxf(m0, fmaxf(a, bb2));
                        unpack2(v1, a, bb2); m1 = fmaxf(m1, fmaxf(a, bb2));
                    }
                    unsigned long long cs = add2(add2(c0, c1), add2(c2, c3));
                    float sa, sbv; unpack2(cs, sa, sbv);
                    float accv = sa + sbv;
                    float m = fmaxf(fmaxf(m0, m1), fmaxf(m2, m3));
                    buf[cur][j] = accv * (1.0f / m) * eecur;
                    Cl += __logf(m);
                }
                barr64();
            }
        }
        const int lastbuf = (xlen >= 2) ? ((xlen - 1) & 1) : 0;
        if (j < NT) red[j] = buf[lastbuf][j] * __expf(Tsh[j * NT + TSTOP]);
        barr64();

        float logZ = 0.f;
        if (tid == 0) {
            float sZ = 0.f;
            for (int i = 0; i < NT; i++) sZ += red[i];
            logZ = Cl + __logf(sZ);
        }
        barr64();

        // gold score
        const int* tg = tags + b * SS;
        {
            float gp = 0.f;
            for (int s = tid; s < xlen; s += 64) {
                int cs = tg[s];
                gp += g_emit[((long long)b * SS + s) * NT + cs];
                if (s >= 1) gp += Tsh[tg[s - 1] * NT + cs];
            }
            red[tid] = gp;
        }
        barr64();
        if (tid == 0) {
            float g = 0.f;
            for (int i = 0; i < 64; i++) g += red[i];
            int li = (xlen > 0) ? (xlen - 1) : 0;
            g += Tsh[TSTART * NT + tg[0]] + Tsh[tg[li] * NT + TSTOP];
            g_lossb[b] = logZ - g;
            __threadfence();
            atomicAdd(&g_nllcnt, 1);
        }
    } else {
        // ---------------- Viterbi ----------------
        unsigned char* bp = reinterpret_cast<unsigned char*>(u.uu);
        float Tcol[NT];
        float TjS = 0.f;
        if (j < NT) {
#pragma unroll
            for (int i = 0; i < NT; i++) Tcol[i] = trans[i * NT + j];
            TjS = trans[j * NT + TSTOP];
        }

        if (tid == 0) { wait_flag(b * 8 + 0); sready = 1; __threadfence(); }
        barr64();

        if (j < NT)
            buf[0][j] = g_emit[(b * SS) * NT + j] + trans[TSTART * NT + j];
        barr64();

        const float* em = g_emit + (long long)b * SS * NT;
        float emnext = (xlen > 1 && j < NT) ? em[NT + j] : 0.f;
        int t = 1;
        for (int c = 0; c <= cmax; c++) {
            const int wc = min(c + 1, cmax);
            if (tid == 0) {
                for (; sready <= wc; sready++) wait_flag(b * 8 + sready);
                __threadfence();
            }
            barr64();
            const int tend = min((c + 1) * 64, xlen);
            for (; t < tend; t++) {
                const int cur = t & 1, prev = cur ^ 1;
                float ec = emnext;
                if (t + 1 < xlen && j < NT) emnext = em[(t + 1) * NT + j];
                if (j < NT) {
                    float bb4[4] = {-1e30f, -1e30f, -1e30f, -1e30f};
                    int   bi4[4] = {0, 9, 18, 27};
#pragma unroll
                    for (int c4 = 0; c4 < 4; c4++) {
#pragma unroll
                        for (int k = 0; k < 9; k++) {
                            int i = c4 * 9 + k;
                            float v = buf[prev][i] + Tcol[i];
                            bool gt = v > bb4[c4];
                            bb4[c4] = gt ? v : bb4[c4];
                            bi4[c4] = gt ? i : bi4[c4];
                        }
                    }
                    float best = bb4[0]; int bi = bi4[0];
                    if (bb4[1] > best) { best = bb4[1]; bi = bi4[1]; }
                    if (bb4[2] > best) { best = bb4[2]; bi = bi4[2]; }
                    if (bb4[3] > best) { best = bb4[3]; bi = bi4[3]; }
                    buf[cur][j] = best + ec;
                    bp[(t - 1) * NT + j] = (unsigned char)bi;
                }
                barr64();
            }
        }
        const int lastbuf = (xlen >= 2) ? ((xlen - 1) & 1) : 0;
        if (j < NT) red[j] = buf[lastbuf][j] + TjS;
        barr64();
        if (tid == 0) {
            float bs = -1e30f; int lt = 0;
            for (int i = 0; i < NT; i++) {
                float v = red[i];
                if (v > bs) { bs = v; lt = i; }
            }
            out[1 + BB * SS + b] = bs;   // path_score
            sh_last = lt;
        }
        barr64();

        float* op = out + 1 + b * SS;
        for (int s = xlen + tid; s < SS; s += 64) op[s] = 0.f;  // masked tail
        if (tid == 0 && xlen > 0) {
            int tag = sh_last;
            op[xlen - 1] = (float)tag;
            for (int t2 = xlen - 1; t2 >= 1; t2--) {
                tag = bp[(t2 - 1) * NT + tag];
                op[t2 - 1] = (float)tag;
            }
        }
    }
}

extern "C" void kernel_launch(void* const* d_in, const int* in_sizes, int n_in,
                              void* d_out, int out_size) {
    const float* x1    = (const float*)d_in[0];
    const int*   hidx  = (const int*)  d_in[1];
    const int*   tags  = (const int*)  d_in[2];
    const float* W     = (const float*)d_in[3];
    const float* bias  = (const float*)d_in[4];
    const float* trans = (const float*)d_in[5];
    float* out = (float*)d_out;

    init_kernel<<<2, 256>>>();
    fused_kernel<<<SCAN_BLOCKS + GEMM_BLOCKS + 1, 128>>>(
        x1, hidx, W, bias, tags, trans, out);
}

// round 9
// speedup vs baseline: 2.0589x; 1.0728x over previous
#include <cuda_runtime.h>
#include <math.h>

#define BB 64
#define SS 512
#define HH 768
#define NT 36
#define TSTART 34
#define TSTOP 35
#define KQ 192             // K per quarter (768/4)
#define SCAN_BLOCKS 128
#define GEMM_BLOCKS 256    // 128 rows per block
#define CHUNK 128          // rows per readiness chunk (4 per batch)

// Scratch (device globals — no allocation allowed)
__device__ float g_emit [BB * SS * NT];
__device__ float g_eemit[BB * SS * NT];
__device__ float g_lossb[BB];
__device__ int   g_done [BB * 4];         // per-(batch,128-chunk) readiness
__device__ int   g_nllcnt;

// ---------------- f32x2 helpers ----------------
__device__ __forceinline__ unsigned long long pack2(float a, float b) {
    unsigned long long r;
    asm("mov.b64 %0, {%1, %2};" : "=l"(r) : "f"(a), "f"(b));
    return r;
}
__device__ __forceinline__ void unpack2(unsigned long long v, float& a, float& b) {
    asm("mov.b64 {%0, %1}, %2;" : "=f"(a), "=f"(b) : "l"(v));
}
__device__ __forceinline__ unsigned long long fma2(unsigned long long a,
                                                   unsigned long long b,
                                                   unsigned long long c) {
    unsigned long long d;
    asm("fma.rn.f32x2 %0, %1, %2, %3;" : "=l"(d) : "l"(a), "l"(b), "l"(c));
    return d;
}
__device__ __forceinline__ unsigned long long add2(unsigned long long a,
                                                   unsigned long long b) {
    unsigned long long d;
    asm("add.rn.f32x2 %0, %1, %2;" : "=l"(d) : "l"(a), "l"(b));
    return d;
}
__device__ __forceinline__ void barr64() {
    asm volatile("bar.sync 0, 64;" ::: "memory");
}
__device__ __forceinline__ void wait_flag(int idx) {
    volatile int* f = &g_done[idx];
    while (*f == 0) __nanosleep(64);
}

// ---------------- init ----------------
__global__ void init_kernel() {
    int i = threadIdx.x + blockIdx.x * blockDim.x;
    if (i < BB * 4) g_done[i] = 0;
    if (i == 0) g_nllcnt = 0;
}

union SmemU {
    float Xs[4][16][128];          // 32768 B  k-major X tiles (per quarter)
    float part[3][128][36];        // 55296 B  quarter partials
    char  uu[(SS - 1) * NT];       // 18396 B  Tsh / backpointers
};

// GEMM inner for one column-half. NP = f32x2 pairs (8 for cols[0,16), 10 for [16,36)).
template<int NP>
__device__ __forceinline__ void gemm_half(
    SmemU* u, const float* __restrict__ x1, const float* __restrict__ W,
    const float* __restrict__ bias, const int* src,
    int q, int h, int lane, int rowbase)
{
    const int coloff = h * 16;
    unsigned long long acc[4][NP];
#pragma unroll
    for (int r4 = 0; r4 < 4; r4++)
#pragma unroll
        for (int p = 0; p < NP; p++) acc[r4][p] = 0ull;

    const int kbase = q * KQ;
    const int tid64 = lane + h * 32;

    for (int kt = 0; kt < KQ / 16; kt++) {
        const int k0 = kbase + kt * 16;
        // stage 128 rows x 16 k for this quarter (both half-warps cooperate)
#pragma unroll
        for (int it = 0; it < 8; it++) {
            int idx = tid64 + it * 64;
            int rr = idx & 127, c4 = idx >> 7;
            float4 v = __ldcg(reinterpret_cast<const float4*>(x1 + src[rr] + k0) + c4);
            u->Xs[q][c4 * 4 + 0][rr] = v.x;
            u->Xs[q][c4 * 4 + 1][rr] = v.y;
            u->Xs[q][c4 * 4 + 2][rr] = v.z;
            u->Xs[q][c4 * 4 + 3][rr] = v.w;
        }
        __syncthreads();

#pragma unroll
        for (int kk = 0; kk < 16; kk++) {
            unsigned long long px[4];
#pragma unroll
            for (int r4 = 0; r4 < 4; r4++) {
                float x = u->Xs[q][kk][lane + 32 * r4];
                px[r4] = pack2(x, x);
            }
            const ulonglong2* wrow =
                reinterpret_cast<const ulonglong2*>(W + (k0 + kk) * 36 + coloff);
#pragma unroll
            for (int p = 0; p < NP / 2; p++) {
                ulonglong2 w = __ldg(wrow + p);     // uniform LDG.128
#pragma unroll
                for (int r4 = 0; r4 < 4; r4++) {
                    acc[r4][2 * p]     = fma2(px[r4], w.x, acc[r4][2 * p]);
                    acc[r4][2 * p + 1] = fma2(px[r4], w.y, acc[r4][2 * p + 1]);
                }
            }
        }
        __syncthreads();
    }

    // write partials (quarters 1..3) / finalize (quarter 0)
    if (q != 0) {
#pragma unroll
        for (int r4 = 0; r4 < 4; r4++) {
            const int row = lane + 32 * r4;
#pragma unroll
            for (int p = 0; p < NP; p++) {
                float a, b; unpack2(acc[r4][p], a, b);
                u->part[q - 1][row][coloff + 2 * p]     = a;
                u->part[q - 1][row][coloff + 2 * p + 1] = b;
            }
        }
    }
    __syncthreads();
    if (q == 0) {
#pragma unroll
        for (int r4 = 0; r4 < 4; r4++) {
            const int row = lane + 32 * r4;
            const long long grow = rowbase + row;
            float ev[2 * NP], eev[2 * NP];
#pragma unroll
            for (int p = 0; p < NP; p++) {
                float a, b; unpack2(acc[r4][p], a, b);
                int c0 = coloff + 2 * p;
                float v0 = a + u->part[0][row][c0] + u->part[1][row][c0] +
                           u->part[2][row][c0] + bias[c0];
                float v1 = b + u->part[0][row][c0 + 1] + u->part[1][row][c0 + 1] +
                           u->part[2][row][c0 + 1] + bias[c0 + 1];
                v0 = (v0 >= 0.f) ? v0 : 0.01f * v0;
                v1 = (v1 >= 0.f) ? v1 : 0.01f * v1;
                ev[2 * p] = v0;  ev[2 * p + 1] = v1;
                eev[2 * p] = __expf(v0);  eev[2 * p + 1] = __expf(v1);
            }
            float4* pe  = reinterpret_cast<float4*>(g_emit  + grow * 36 + coloff);
            float4* pee = reinterpret_cast<float4*>(g_eemit + grow * 36 + coloff);
#pragma unroll
            for (int c4 = 0; c4 < NP / 2; c4++) {
                pe[c4]  = make_float4(ev[4*c4],  ev[4*c4+1],  ev[4*c4+2],  ev[4*c4+3]);
                pee[c4] = make_float4(eev[4*c4], eev[4*c4+1], eev[4*c4+2], eev[4*c4+3]);
            }
        }
    }
}

// ---------------- fused kernel ----------------
// blocks [0,64):    NLL scan (batch bid)
// blocks [64,128):  Viterbi (batch bid-64)
// blocks [128,384): GEMM, chunk-major: c=(bid-128)>>6, b=(bid-128)&63, 128 rows
// block  384:       loss reducer
__global__ __launch_bounds__(256, 2) void fused_kernel(
    const float* __restrict__ x1, const int* __restrict__ hidx,
    const float* __restrict__ W, const float* __restrict__ bias,
    const int* __restrict__ tags, const float* __restrict__ trans,
    float* __restrict__ out)
{
    __shared__ __align__(16) SmemU u;
    __shared__ int   src[128];
    __shared__ __align__(16) float buf[2][NT];
    __shared__ float red[64];
    __shared__ int   ired[64];
    __shared__ int   sh_xlen, sh_last;

    const int tid = threadIdx.x;
    const int bid = blockIdx.x;

    if (bid >= SCAN_BLOCKS && bid < SCAN_BLOCKS + GEMM_BLOCKS) {
        // ================= GEMM =================
        const int gb = bid - SCAN_BLOCKS;
        const int c  = gb >> 6;          // chunk 0..3
        const int b  = gb & 63;          // batch
        const int rowbase = b * SS + c * CHUNK;
        const int warp = tid >> 5;
        const int q = warp >> 1;         // k-quarter
        const int h = warp & 1;          // col half
        const int lane = tid & 31;

        if (tid < 128) {
            int g = rowbase + tid;
            src[tid] = (b << 9) * HH + hidx[g] * HH;
        }
        __syncthreads();

        if (h == 0) gemm_half<8 >(&u, x1, W, bias, src, q, 0, lane, rowbase);
        else        gemm_half<10>(&u, x1, W, bias, src, q, 1, lane, rowbase);

        __syncthreads();
        if (tid == 0) {
            __threadfence();
            atomicExch(&g_done[b * 4 + c], 1);
        }
        return;
    }

    if (bid >= SCAN_BLOCKS + GEMM_BLOCKS) {
        // ================= loss reducer =================
        if (tid == 0) {
            volatile int* c = &g_nllcnt;
            while (*c < BB) __nanosleep(256);
            __threadfence();
            float a = 0.f;
            for (int i = 0; i < BB; i++) a += g_lossb[i];
            out[0] = a;
        }
        return;
    }

    // ================= SCANS (threads 0-63 only) =================
    if (tid >= 64) return;

    const int b = bid & 63;
    const bool viterbi = (bid >= BB);
    const int j = tid;

    // xlen = max(head_indexes[b, :])
    {
        int lm = 0;
        for (int s = tid; s < SS; s += 64) lm = max(lm, hidx[b * SS + s]);
        ired[tid] = lm;
        barr64();
        if (tid == 0) {
            int m = 0;
            for (int i = 0; i < 64; i++) m = max(m, ired[i]);
            sh_xlen = m;
        }
        barr64();
    }
    const int xlen = sh_xlen;
    const int cmax = (xlen - 1) >> 7;    // 128-row chunks
    int sready = 0;

    if (!viterbi) {
        // ---------------- NLL (scaled forward) ----------------
        float* Tsh = reinterpret_cast<float*>(u.uu);
        for (int i = tid; i < NT * NT; i += 64) Tsh[i] = trans[i];
        barr64();

        unsigned long long Ecol2[18];
        float Cl = 0.f;
        if (j < NT) {
#pragma unroll
            for (int p = 0; p < 18; p++)
                Ecol2[p] = pack2(__expf(Tsh[(2 * p) * NT + j]),
                                 __expf(Tsh[(2 * p + 1) * NT + j]));
        }

        if (tid == 0) { wait_flag(b * 4 + 0); sready = 1; __threadfence(); }
        barr64();

        if (j < NT)
            buf[0][j] = __expf(g_emit[(b * SS) * NT + j] + Tsh[TSTART * NT + j]);
        barr64();

        const float* ee = g_eemit + (long long)b * SS * NT;
        float eenext = (xlen > 1 && j < NT) ? ee[NT + j] : 0.f;
        int t = 1;
        for (int c = 0; c <= cmax; c++) {
            const int wc = min(c + 1, cmax);
            if (tid == 0) {
                for (; sready <= wc; sready++) wait_flag(b * 4 + sready);
                __threadfence();
            }
            barr64();
            const int tend = min((c + 1) * CHUNK, xlen);
            for (; t < tend; t++) {
                const int cur = t & 1, prev = cur ^ 1;
                float eecur = eenext;
                if (t + 1 < xlen && j < NT) eenext = ee[(t + 1) * NT + j];
                if (j < NT) {
                    const unsigned long long* vp =
                        reinterpret_cast<const unsigned long long*>(&buf[prev][0]);
                    unsigned long long c0 = 0, c1 = 0, c2 = 0, c3 = 0;
                    float m0 = 0.f, m1 = 0.f, m2 = 0.f, m3 = 0.f;
#pragma unroll
                    for (int p = 0; p < 16; p += 4) {
                        unsigned long long v0 = vp[p], v1 = vp[p+1], v2 = vp[p+2], v3 = vp[p+3];
                        c0 = fma2(v0, Ecol2[p],   c0);
                        c1 = fma2(v1, Ecol2[p+1], c1);
                        c2 = fma2(v2, Ecol2[p+2], c2);
                        c3 = fma2(v3, Ecol2[p+3], c3);
                        float a, bb2;
                        unpack2(v0, a, bb2); m0 = fmaxf(m0, fmaxf(a, bb2));
                        unpack2(v1, a, bb2); m1 = fmaxf(m1, fmaxf(a, bb2));
                        unpack2(v2, a, bb2); m2 = fmaxf(m2, fmaxf(a, bb2));
                        unpack2(v3, a, bb2); m3 = fmaxf(m3, fmaxf(a, bb2));
                    }
                    {
                        unsigned long long v0 = vp[16], v1 = vp[17];
                        c0 = fma2(v0, Ecol2[16], c0);
                        c1 = fma2(v1, Ecol2[17], c1);
                        float a, bb2;
                        unpack2(v0, a, bb2); m0 = fmaxf(m0, fmaxf(a, bb2));
                        unpack2(v1, a, bb2); m1 = fmaxf(m1, fmaxf(a, bb2));
                    }
                    unsigned long long cs = add2(add2(c0, c1), add2(c2, c3));
                    float sa, sbv; unpack2(cs, sa, sbv);
                    float accv = sa + sbv;
                    float m = fmaxf(fmaxf(m0, m1), fmaxf(m2, m3));
                    buf[cur][j] = accv * (1.0f / m) * eecur;
                    Cl += __logf(m);
                }
                barr64();
            }
        }
        const int lastbuf = (xlen >= 2) ? ((xlen - 1) & 1) : 0;
        if (j < NT) red[j] = buf[lastbuf][j] * __expf(Tsh[j * NT + TSTOP]);
        barr64();

        float logZ = 0.f;
        if (tid == 0) {
            float sZ = 0.f;
            for (int i = 0; i < NT; i++) sZ += red[i];
            logZ = Cl + __logf(sZ);
        }
        barr64();

        // gold score
        const int* tg = tags + b * SS;
        {
            float gp = 0.f;
            for (int s = tid; s < xlen; s += 64) {
                int cs = tg[s];
                gp += g_emit[((long long)b * SS + s) * NT + cs];
                if (s >= 1) gp += Tsh[tg[s - 1] * NT + cs];
            }
            red[tid] = gp;
        }
        barr64();
        if (tid == 0) {
            float g = 0.f;
            for (int i = 0; i < 64; i++) g += red[i];
            int li = (xlen > 0) ? (xlen - 1) : 0;
            g += Tsh[TSTART * NT + tg[0]] + Tsh[tg[li] * NT + TSTOP];
            g_lossb[b] = logZ - g;
            __threadfence();
            atomicAdd(&g_nllcnt, 1);
        }
    } else {
        // ---------------- Viterbi ----------------
        unsigned char* bp = reinterpret_cast<unsigned char*>(u.uu);
        float Tcol[NT];
        float TjS = 0.f;
        if (j < NT) {
#pragma unroll
            for (int i = 0; i < NT; i++) Tcol[i] = trans[i * NT + j];
            TjS = trans[j * NT + TSTOP];
        }

        if (tid == 0) { wait_flag(b * 4 + 0); sready = 1; __threadfence(); }
        barr64();

        if (j < NT)
            buf[0][j] = g_emit[(b * SS) * NT + j] + trans[TSTART * NT + j];
        barr64();

        const float* em = g_emit + (long long)b * SS * NT;
        float emnext = (xlen > 1 && j < NT) ? em[NT + j] : 0.f;
        int t = 1;
        for (int c = 0; c <= cmax; c++) {
            const int wc = min(c + 1, cmax);
            if (tid == 0) {
                for (; sready <= wc; sready++) wait_flag(b * 4 + sready);
                __threadfence();
            }
            barr64();
            const int tend = min((c + 1) * CHUNK, xlen);
            for (; t < tend; t++) {
                const int cur = t & 1, prev = cur ^ 1;
                float ec = emnext;
                if (t + 1 < xlen && j < NT) emnext = em[(t + 1) * NT + j];
                if (j < NT) {
                    float bb4[4] = {-1e30f, -1e30f, -1e30f, -1e30f};
                    int   bi4[4] = {0, 9, 18, 27};
#pragma unroll
                    for (int c4 = 0; c4 < 4; c4++) {
#pragma unroll
                        for (int k = 0; k < 9; k++) {
                            int i = c4 * 9 + k;
                            float v = buf[prev][i] + Tcol[i];
                            bool gt = v > bb4[c4];
                            bb4[c4] = gt ? v : bb4[c4];
                            bi4[c4] = gt ? i : bi4[c4];
                        }
                    }
                    float best = bb4[0]; int bi = bi4[0];
                    if (bb4[1] > best) { best = bb4[1]; bi = bi4[1]; }
                    if (bb4[2] > best) { best = bb4[2]; bi = bi4[2]; }
                    if (bb4[3] > best) { best = bb4[3]; bi = bi4[3]; }
                    buf[cur][j] = best + ec;
                    bp[(t - 1) * NT + j] = (unsigned char)bi;
                }
                barr64();
            }
        }
        const int lastbuf = (xlen >= 2) ? ((xlen - 1) & 1) : 0;
        if (j < NT) red[j] = buf[lastbuf][j] + TjS;
        barr64();
        if (tid == 0) {
            float bs = -1e30f; int lt = 0;
            for (int i = 0; i < NT; i++) {
                float v = red[i];
                if (v > bs) { bs = v; lt = i; }
            }
            out[1 + BB * SS + b] = bs;   // path_score
            sh_last = lt;
        }
        barr64();

        float* op = out + 1 + b * SS;
        for (int s = xlen + tid; s < SS; s += 64) op[s] = 0.f;
        if (tid == 0 && xlen > 0) {
            int tag = sh_last;
            op[xlen - 1] = (float)tag;
            for (int t2 = xlen - 1; t2 >= 1; t2--) {
                tag = bp[(t2 - 1) * NT + tag];
                op[t2 - 1] = (float)tag;
            }
        }
    }
}

extern "C" void kernel_launch(void* const* d_in, const int* in_sizes, int n_in,
                              void* d_out, int out_size) {
    const float* x1    = (const float*)d_in[0];
    const int*   hidx  = (const int*)  d_in[1];
    const int*   tags  = (const int*)  d_in[2];
    const float* W     = (const float*)d_in[3];
    const float* bias  = (const float*)d_in[4];
    const float* trans = (const float*)d_in[5];
    float* out = (float*)d_out;

    init_kernel<<<1, 256>>>();
    fused_kernel<<<SCAN_BLOCKS + GEMM_BLOCKS + 1, 256>>>(
        x1, hidx, W, bias, tags, trans, out);
}